// round 2
// baseline (speedup 1.0000x reference)
#include <cuda_runtime.h>

#define KK    64
#define S1C   5
#define CC    128
#define MM    320         // KK*S1C
#define PP    1936        // 44*44
#define NN    8
#define PT    64          // pixels per tile
#define TILES 31          // ceil(1936/64)
#define ALPHA_C 1500.0f
#define EPS_C   1e-12f

// ---- device scratch (static: no allocations allowed) ----
__device__ float g_w[160 * 256];              // w interleaved: [pair][c][2], w[2mp+j][c] = g_w[mp*256 + c*2 + j]
__device__ float g_b[MM];
__device__ float g_part[NN * TILES * KK * CC];  // per-tile partial out accumulators (~8.1 MB)
__device__ float g_sumw[NN * TILES * KK];
__device__ float g_outn[NN * KK * CC];
__device__ float g_rowss[NN * KK];

// ---- f32x2 helpers (ptxas never auto-emits FFMA2; B300 fma pipe is 2x wider via f32x2) ----
__device__ __forceinline__ unsigned long long dup2(float v) {
    unsigned long long r;
    asm("mov.b64 %0, {%1, %1};" : "=l"(r) : "f"(v));
    return r;
}
__device__ __forceinline__ void fma2(unsigned long long& d, unsigned long long a, unsigned long long b) {
    asm("fma.rn.f32x2 %0, %1, %2, %0;" : "+l"(d) : "l"(a), "l"(b));
}
__device__ __forceinline__ float2 unpack2(unsigned long long v) {
    float2 r;
    asm("mov.b64 {%0, %1}, %2;" : "=f"(r.x), "=f"(r.y) : "l"(v));
    return r;
}

// ======================= prep: build interleaved w and b =======================
__global__ void prep_kernel(const float* __restrict__ cent) {
    int m = blockIdx.x * 8 + (threadIdx.x >> 5);
    int lane = threadIdx.x & 31;
    if (m >= MM) return;
    float4 v = *(const float4*)(cent + m * CC + lane * 4);
    float ss = v.x * v.x + v.y * v.y + v.z * v.z + v.w * v.w;
    #pragma unroll
    for (int o = 16; o; o >>= 1) ss += __shfl_xor_sync(0xffffffffu, ss, o);
    if (lane == 0) g_b[m] = -ALPHA_C * sqrtf(ss);
    int mp = m >> 1, j = m & 1;
    float* wr = g_w + mp * 256 + j;
    int c = lane * 4;
    wr[(c + 0) * 2] = 2.0f * ALPHA_C * v.x;
    wr[(c + 1) * 2] = 2.0f * ALPHA_C * v.y;
    wr[(c + 2) * 2] = 2.0f * ALPHA_C * v.z;
    wr[(c + 3) * 2] = 2.0f * ALPHA_C * v.w;
}

// ======================= fused main kernel =======================
// block = (n, pixel-tile of 64). smem (230656 B):
//   xs : float2[64][65]   x tile as [c2][p] pairs {x[2c2][p], x[2c2+1][p]}   (33280 B)
//   ws : float2[80][128]  one 160-row w chunk, m-pair interleaved             (81920 B)
//   lg : float[64][321]   logits, row per pixel (padded)                      (82176 B)
//   was: float2[64][65]   {wa,wa} duplicated w_assign                         (33280 B)
__global__ __launch_bounds__(512, 1)
void main_kernel(const float* __restrict__ x, float* __restrict__ sa_out) {
    extern __shared__ float smem[];
    float* xs  = smem;                  // 8320 floats
    float* ws  = smem + 8320;           // 20480 floats
    float* lg  = smem + 8320 + 20480;   // 20544 floats
    float* was = lg + 20544;            // 8320 floats

    int tid = threadIdx.x;
    int bx = blockIdx.x;
    int n = bx / TILES, tile = bx % TILES;
    int p0 = tile * PT;
    int pvalid = min(PT, PP - p0);

    // ---- load x tile: xs[(c>>1)*65 + p] .x/.y ----
    {
        int c = tid >> 2;
        int lane4 = tid & 3;
        const float* src = x + (n * CC + c) * PP + p0;
        int half = c & 1, c2 = c >> 1;
        #pragma unroll
        for (int u = 0; u < 16; u++) {
            int p = u * 4 + lane4;
            float v = (p0 + p < PP) ? src[p] : 0.0f;
            xs[(c2 * 65 + p) * 2 + half] = v;
        }
    }

    // ---- phase 1: logits GEMM in f32x2 (m-pair packed) ----
    int pg = tid & 31;   // p pair base = pg*2 ; warp shares mg -> broadcast w loads
    int mg = tid >> 5;   // 5 m-pairs per thread per chunk

    for (int chunk = 0; chunk < 2; chunk++) {
        __syncthreads();
        {   // stream w chunk (80 KB)
            const float4* wsrc = (const float4*)(g_w + chunk * 20480);
            float4* wdst = (float4*)ws;
            #pragma unroll
            for (int i = 0; i < 10; i++) wdst[tid + i * 512] = wsrc[tid + i * 512];
        }
        __syncthreads();

        unsigned long long acc[5][2];
        #pragma unroll
        for (int i = 0; i < 5; i++) { acc[i][0] = 0ull; acc[i][1] = 0ull; }

        const float* wbase = ws + (mg * 5) * 256;
        #pragma unroll 4
        for (int c2 = 0; c2 < 64; c2++) {
            const float* xrow = xs + c2 * 130;  // (c2*65)*2
            float2 xv0 = *(const float2*)(xrow + pg * 4);
            float2 xv1 = *(const float2*)(xrow + pg * 4 + 2);
            unsigned long long xa0 = dup2(xv0.x), xb0 = dup2(xv0.y);
            unsigned long long xa1 = dup2(xv1.x), xb1 = dup2(xv1.y);
            #pragma unroll
            for (int i = 0; i < 5; i++) {
                ulonglong2 wv = *(const ulonglong2*)(wbase + i * 256 + c2 * 4);
                fma2(acc[i][0], wv.x, xa0);
                fma2(acc[i][1], wv.x, xa1);
                fma2(acc[i][0], wv.y, xb0);
                fma2(acc[i][1], wv.y, xb1);
            }
        }

        // write logits (+ bias)
        #pragma unroll
        for (int i = 0; i < 5; i++) {
            int m = chunk * 160 + 2 * (mg * 5 + i);
            float b0 = g_b[m], b1 = g_b[m + 1];
            #pragma unroll
            for (int j = 0; j < 2; j++) {
                float2 a = unpack2(acc[i][j]);
                int p = pg * 2 + j;
                lg[p * 321 + m]     = a.x + b0;
                lg[p * 321 + m + 1] = a.y + b1;
            }
        }
    }
    __syncthreads();

    // ---- softmax epilogue: warp handles 4 pixels; lane handles k=lane and k=lane+32 ----
    {
        int wid = tid >> 5, lane = tid & 31;
        #pragma unroll
        for (int pi = 0; pi < 4; pi++) {
            int p = wid * 4 + pi;
            const float* row = lg + p * 321;
            float l0a, l0b, beta_a, beta_b;
            {
                const float* q = row + lane * 5;
                float v0 = q[0], v1 = q[1], v2 = q[2], v3 = q[3], v4 = q[4];
                float bm = fmaxf(fmaxf(fmaxf(v0, v1), fmaxf(v2, v3)), v4);
                float bs = __expf(v0 - bm) + __expf(v1 - bm) + __expf(v2 - bm)
                         + __expf(v3 - bm) + __expf(v4 - bm);
                beta_a = __expf(v0 - bm) / bs;
                l0a = v0;
            }
            {
                const float* q = row + lane * 5 + 160;
                float v0 = q[0], v1 = q[1], v2 = q[2], v3 = q[3], v4 = q[4];
                float bm = fmaxf(fmaxf(fmaxf(v0, v1), fmaxf(v2, v3)), v4);
                float bs = __expf(v0 - bm) + __expf(v1 - bm) + __expf(v2 - bm)
                         + __expf(v3 - bm) + __expf(v4 - bm);
                beta_b = __expf(v0 - bm) / bs;
                l0b = v0;
            }
            float am = fmaxf(l0a, l0b);
            #pragma unroll
            for (int o = 16; o; o >>= 1) am = fmaxf(am, __shfl_xor_sync(0xffffffffu, am, o));
            float ea = __expf(l0a - am), eb = __expf(l0b - am);
            float es = ea + eb;
            #pragma unroll
            for (int o = 16; o; o >>= 1) es += __shfl_xor_sync(0xffffffffu, es, o);
            float inv = 1.0f / es;
            float sa0 = ea * inv * beta_a;
            float sa1 = eb * inv * beta_b;
            float w0 = (p < pvalid) ? (1.0f + sa0) : 0.0f;
            float w1 = (p < pvalid) ? (1.0f + sa1) : 0.0f;
            *(float2*)(was + (lane * 65 + p) * 2)        = make_float2(w0, w0);
            *(float2*)(was + ((lane + 32) * 65 + p) * 2) = make_float2(w1, w1);
        }
    }
    __syncthreads();

    // ---- write soft_assign (coalesced: 8 threads per k row) ----
    {
        int k = tid >> 3, seg = tid & 7;
        float* dst = sa_out + (n * KK + k) * PP + p0;
        #pragma unroll
        for (int u = 0; u < 8; u++) {
            int p = seg * 8 + u;
            if (p < pvalid) dst[p] = was[(k * 65 + p) * 2] - 1.0f;
        }
    }

    // ---- phase 2: out_part[k][c] = sum_p wa[k][p] * x[c][p], f32x2 over c-pairs ----
    {
        int cg = tid & 31, kg = tid >> 5;
        unsigned long long a2[4][2];
        #pragma unroll
        for (int i = 0; i < 4; i++) { a2[i][0] = 0ull; a2[i][1] = 0ull; }
        #pragma unroll 4
        for (int p = 0; p < 64; p++) {
            unsigned long long xv0 = *(const unsigned long long*)(xs + (cg * 65 + p) * 2);
            unsigned long long xv1 = *(const unsigned long long*)(xs + ((cg + 32) * 65 + p) * 2);
            #pragma unroll
            for (int q = 0; q < 4; q++) {
                unsigned long long wv = *(const unsigned long long*)(was + ((kg * 4 + q) * 65 + p) * 2);
                fma2(a2[q][0], wv, xv0);
                fma2(a2[q][1], wv, xv1);
            }
        }
        float* pb = g_part + bx * 8192;
        #pragma unroll
        for (int q = 0; q < 4; q++) {
            int k = kg * 4 + q;
            #pragma unroll
            for (int j = 0; j < 2; j++) {
                int c2 = cg + 32 * j;
                float2 r = unpack2(a2[q][j]);
                *(float2*)(pb + k * 128 + c2 * 2) = r;
            }
        }
    }

    // ---- sumw partials ----
    if (tid < 64) {
        float s = 0.0f;
        #pragma unroll 8
        for (int p = 0; p < 64; p++) s += was[(tid * 65 + p) * 2];
        g_sumw[bx * 64 + tid] = s;
    }
}

// ======================= finalize 1: reduce tiles, subtract rep*sumw, intra-norm =======================
__global__ void finalize1(const float* __restrict__ cent) {
    int n = blockIdx.x >> 6, k = blockIdx.x & 63;
    int c = threadIdx.x;  // 128 threads
    float acc = 0.0f;
    const float* pb = g_part + (n * TILES) * 8192 + k * 128 + c;
    #pragma unroll
    for (int t = 0; t < TILES; t++) acc += pb[t * 8192];
    float sw = 0.0f;
    const float* sb = g_sumw + n * TILES * 64 + k;
    #pragma unroll
    for (int t = 0; t < TILES; t++) sw += sb[t * 64];
    float rep = cent[k * S1C * CC + c];
    float v = acc - rep * sw;
    float ss = v * v;
    #pragma unroll
    for (int o = 16; o; o >>= 1) ss += __shfl_xor_sync(0xffffffffu, ss, o);
    __shared__ float sred[4];
    if ((threadIdx.x & 31) == 0) sred[threadIdx.x >> 5] = ss;
    __syncthreads();
    float tot = sred[0] + sred[1] + sred[2] + sred[3];
    float rn = fmaxf(sqrtf(tot), EPS_C);
    g_outn[(n * 64 + k) * 128 + c] = v / rn;
    if (threadIdx.x == 0) g_rowss[n * 64 + k] = tot / (rn * rn);
}

// ======================= finalize 2: global L2 norm per n, write flat =======================
__global__ void finalize2(float* __restrict__ out) {
    int n = blockIdx.x;
    __shared__ float sred[64];
    int tid = threadIdx.x;  // 512
    if (tid < 64) sred[tid] = g_rowss[n * 64 + tid];
    __syncthreads();
    if (tid == 0) {
        float t = 0.0f;
        #pragma unroll
        for (int i = 0; i < 64; i++) t += sred[i];
        sred[0] = 1.0f / fmaxf(sqrtf(t), EPS_C);
    }
    __syncthreads();
    float sc = sred[0];
    for (int i = tid; i < 8192; i += 512)
        out[n * 8192 + i] = g_outn[n * 8192 + i] * sc;
}

extern "C" void kernel_launch(void* const* d_in, const int* in_sizes, int n_in,
                              void* d_out, int out_size) {
    const float* x    = (const float*)d_in[0];   // (8,128,44,44)
    const float* cent = (const float*)d_in[1];   // (64,5,128)
    float* out = (float*)d_out;                  // [flat (8,8192) | soft_assign (8,64,1,1936)]
    float* sa = out + NN * KK * CC;

    static_assert(8320 * 4 + 20480 * 4 + 20544 * 4 + 8320 * 4 == 230656, "smem layout");
    cudaFuncSetAttribute(main_kernel, cudaFuncAttributeMaxDynamicSharedMemorySize, 230656);

    prep_kernel<<<40, 256>>>(cent);
    main_kernel<<<NN * TILES, 512, 230656>>>(x, sa);
    finalize1<<<NN * KK, 128>>>(cent);
    finalize2<<<NN, 512>>>(out);
}